// round 1
// baseline (speedup 1.0000x reference)
#include <cuda_runtime.h>
#include <cuda_bf16.h>
#include <cstdint>

// Problem constants
#define BROWS 32768
#define DMODEL 2048
#define NEXP 4
#define DEXP 512

// Scratch (device globals: allocation-free rule)
__device__ float g_xn[(size_t)BROWS * DMODEL];
__device__ float g_v [(size_t)BROWS * DMODEL];
__device__ float g_eo[(size_t)BROWS * DMODEL];
__device__ float g_rt[(size_t)BROWS * NEXP];

// ---------------------------------------------------------------------------
// Kernel 0: RMSNorm + router softmax (one block per row)
// ---------------------------------------------------------------------------
__global__ void __launch_bounds__(256)
rmsnorm_router_kernel(const float* __restrict__ x, const float* __restrict__ nw,
                      const float* __restrict__ rw, const float* __restrict__ rb,
                      float* __restrict__ xn, float* __restrict__ routing)
{
    __shared__ float red[8];
    __shared__ float red4[8][4];
    __shared__ float s_rn;

    const int b = blockIdx.x;
    const int tid = threadIdx.x;
    const int lane = tid & 31, warp = tid >> 5;

    const float4* xr = reinterpret_cast<const float4*>(x + (size_t)b * DMODEL);
    float4 v0 = xr[tid];
    float4 v1 = xr[tid + 256];

    float ss = v0.x*v0.x + v0.y*v0.y + v0.z*v0.z + v0.w*v0.w
             + v1.x*v1.x + v1.y*v1.y + v1.z*v1.z + v1.w*v1.w;
    #pragma unroll
    for (int o = 16; o; o >>= 1) ss += __shfl_xor_sync(0xffffffffu, ss, o);
    if (lane == 0) red[warp] = ss;
    __syncthreads();
    if (tid == 0) {
        float t = 0.f;
        #pragma unroll
        for (int i = 0; i < 8; i++) t += red[i];
        s_rn = rsqrtf(t * (1.0f / DMODEL) + 1e-6f);
    }
    __syncthreads();
    const float rn = s_rn;

    const float4* nwr = reinterpret_cast<const float4*>(nw);
    float4 w0 = nwr[tid], w1 = nwr[tid + 256];
    float4 y0 = make_float4(v0.x*rn*w0.x, v0.y*rn*w0.y, v0.z*rn*w0.z, v0.w*rn*w0.w);
    float4 y1 = make_float4(v1.x*rn*w1.x, v1.y*rn*w1.y, v1.z*rn*w1.z, v1.w*rn*w1.w);

    float4* xo = reinterpret_cast<float4*>(xn + (size_t)b * DMODEL);
    xo[tid] = y0;
    xo[tid + 256] = y1;

    // router partials: rw is [D,4] row-major, each row is a float4
    const float4* rwr = reinterpret_cast<const float4*>(rw);
    float a0 = 0.f, a1 = 0.f, a2 = 0.f, a3 = 0.f;
    const int d0 = tid * 4;
    const int d1 = (tid + 256) * 4;
    float ys[8] = {y0.x, y0.y, y0.z, y0.w, y1.x, y1.y, y1.z, y1.w};
    int   ds[8] = {d0, d0+1, d0+2, d0+3, d1, d1+1, d1+2, d1+3};
    #pragma unroll
    for (int i = 0; i < 8; i++) {
        float4 w = rwr[ds[i]];
        a0 += ys[i] * w.x; a1 += ys[i] * w.y; a2 += ys[i] * w.z; a3 += ys[i] * w.w;
    }
    #pragma unroll
    for (int o = 16; o; o >>= 1) {
        a0 += __shfl_xor_sync(0xffffffffu, a0, o);
        a1 += __shfl_xor_sync(0xffffffffu, a1, o);
        a2 += __shfl_xor_sync(0xffffffffu, a2, o);
        a3 += __shfl_xor_sync(0xffffffffu, a3, o);
    }
    if (lane == 0) { red4[warp][0]=a0; red4[warp][1]=a1; red4[warp][2]=a2; red4[warp][3]=a3; }
    __syncthreads();
    if (tid == 0) {
        float l[4];
        #pragma unroll
        for (int e = 0; e < 4; e++) {
            l[e] = rb[e];
            #pragma unroll
            for (int i = 0; i < 8; i++) l[e] += red4[i][e];
        }
        float m = fmaxf(fmaxf(l[0], l[1]), fmaxf(l[2], l[3]));
        float p[4], s = 0.f;
        #pragma unroll
        for (int e = 0; e < 4; e++) { p[e] = expf(l[e] - m); s += p[e]; }
        float inv = 1.0f / s;
        #pragma unroll
        for (int e = 0; e < 4; e++) routing[(size_t)b * 4 + e] = p[e] * inv;
    }
}

// ---------------------------------------------------------------------------
// tf32 tensor-core GEMM, 128x128x16 tiles, cp.async double buffer
// MODE 0: C = A@B
// MODE 1: C = (A@B + bias[col]) * routing[row*4 + blockIdx.z]
// MODE 2: C = A@B + resid[row, col]
// ---------------------------------------------------------------------------
__device__ __forceinline__ uint32_t f2tf32(float f) {
    uint32_t u;
    asm("cvt.rna.tf32.f32 %0, %1;" : "=r"(u) : "f"(f));
    return u;
}

#define CP16(dst, src) \
    asm volatile("cp.async.cg.shared.global [%0], [%1], 16;\n" :: "r"(dst), "l"(src))

template<int MODE>
__global__ void __launch_bounds__(256)
gemm_tf32(const float* __restrict__ A, int lda, long long sA,
          const float* __restrict__ B, int ldb, long long sB,
          float* __restrict__ C, int ldc, long long sC,
          int K,
          const float* __restrict__ bias, long long sBias,
          const float* __restrict__ routing,
          const float* __restrict__ resid, int ldr)
{
    constexpr int BM = 128, BN = 128, BK = 16;
    constexpr int LA = 20;    // As[m][k], stride 20 -> conflict-free frag loads
    constexpr int LB = 136;   // Bs[k][n], stride 136 -> conflict-free frag loads
    __shared__ float As[2][BM * LA];
    __shared__ float Bs[2][BK * LB];

    const int e = blockIdx.z;
    A += (long long)e * sA;
    B += (long long)e * sB;
    C += (long long)e * sC;
    if (MODE == 1) bias += (long long)e * sBias;

    const int tid = threadIdx.x;
    const int warp = tid >> 5, lane = tid & 31;
    const int wm = warp & 3, wn = warp >> 2;          // 4 warps in M, 2 in N
    const int gid = lane >> 2, tig = lane & 3;
    const int m0 = wm * 32, n0 = wn * 64;

    const size_t bm = blockIdx.y;
    const size_t bn = blockIdx.x;
    const float* Ag = A + bm * BM * (size_t)lda;
    const float* Bg = B + bn * BN;

    // global->shared load layout
    const int ar = tid >> 2;           // A rows: ar, ar+64
    const int ac = (tid & 3) * 4;      // A col group
    const int br = tid >> 5;           // B k-rows: br, br+8
    const int bc = lane * 4;           // B col group

    const uint32_t as_base = (uint32_t)__cvta_generic_to_shared(&As[0][0]);
    const uint32_t bs_base = (uint32_t)__cvta_generic_to_shared(&Bs[0][0]);

    auto load_stage = [&](int s, int kt) {
        const float* a0p = Ag + (size_t)ar * lda + kt * BK + ac;
        const float* a1p = a0p + (size_t)64 * lda;
        CP16(as_base + (uint32_t)(s * BM * LA + ar * LA + ac) * 4u, a0p);
        CP16(as_base + (uint32_t)(s * BM * LA + (ar + 64) * LA + ac) * 4u, a1p);
        const float* b0p = Bg + (size_t)(kt * BK + br) * ldb + bc;
        const float* b1p = b0p + (size_t)8 * ldb;
        CP16(bs_base + (uint32_t)(s * BK * LB + br * LB + bc) * 4u, b0p);
        CP16(bs_base + (uint32_t)(s * BK * LB + (br + 8) * LB + bc) * 4u, b1p);
        asm volatile("cp.async.commit_group;\n" ::);
    };

    float acc[2][8][4];
    #pragma unroll
    for (int mt = 0; mt < 2; mt++)
        #pragma unroll
        for (int nt = 0; nt < 8; nt++)
            #pragma unroll
            for (int i = 0; i < 4; i++) acc[mt][nt][i] = 0.f;

    const int NT = K / BK;
    load_stage(0, 0);

    for (int kt = 0; kt < NT; kt++) {
        const int st = kt & 1;
        if (kt + 1 < NT) {
            load_stage((kt + 1) & 1, kt + 1);
            asm volatile("cp.async.wait_group 1;\n" ::);
        } else {
            asm volatile("cp.async.wait_group 0;\n" ::);
        }
        __syncthreads();

        const float* as_ = As[st];
        const float* bs_ = Bs[st];
        #pragma unroll
        for (int ks = 0; ks < 2; ks++) {
            uint32_t af[2][4], bf[8][2];
            const int col = ks * 8 + tig;
            #pragma unroll
            for (int mt = 0; mt < 2; mt++) {
                const int r = m0 + mt * 16 + gid;
                af[mt][0] = f2tf32(as_[r * LA + col]);
                af[mt][1] = f2tf32(as_[(r + 8) * LA + col]);
                af[mt][2] = f2tf32(as_[r * LA + col + 4]);
                af[mt][3] = f2tf32(as_[(r + 8) * LA + col + 4]);
            }
            const int kr = ks * 8 + tig;
            #pragma unroll
            for (int nt = 0; nt < 8; nt++) {
                const int c = n0 + nt * 8 + gid;
                bf[nt][0] = f2tf32(bs_[kr * LB + c]);
                bf[nt][1] = f2tf32(bs_[(kr + 4) * LB + c]);
            }
            #pragma unroll
            for (int mt = 0; mt < 2; mt++)
                #pragma unroll
                for (int nt = 0; nt < 8; nt++) {
                    float* d = acc[mt][nt];
                    asm volatile(
                        "mma.sync.aligned.m16n8k8.row.col.f32.tf32.tf32.f32 "
                        "{%0,%1,%2,%3}, {%4,%5,%6,%7}, {%8,%9}, {%0,%1,%2,%3};\n"
                        : "+f"(d[0]), "+f"(d[1]), "+f"(d[2]), "+f"(d[3])
                        : "r"(af[mt][0]), "r"(af[mt][1]), "r"(af[mt][2]), "r"(af[mt][3]),
                          "r"(bf[nt][0]), "r"(bf[nt][1]));
                }
        }
        __syncthreads();
    }

    // epilogue
    const size_t growb = bm * BM;
    const int gcolb = (int)(bn * BN);
    #pragma unroll
    for (int mt = 0; mt < 2; mt++) {
        const size_t r0 = growb + m0 + mt * 16 + gid;
        const size_t r1 = r0 + 8;
        float rt0 = 1.f, rt1 = 1.f;
        if (MODE == 1) {
            rt0 = routing[r0 * 4 + e];
            rt1 = routing[r1 * 4 + e];
        }
        #pragma unroll
        for (int nt = 0; nt < 8; nt++) {
            const int gc = gcolb + n0 + nt * 8 + tig * 2;
            float v0 = acc[mt][nt][0], v1 = acc[mt][nt][1];
            float v2 = acc[mt][nt][2], v3 = acc[mt][nt][3];
            if (MODE == 1) {
                const float b0 = bias[gc], b1 = bias[gc + 1];
                v0 = (v0 + b0) * rt0; v1 = (v1 + b1) * rt0;
                v2 = (v2 + b0) * rt1; v3 = (v3 + b1) * rt1;
            }
            if (MODE == 2) {
                const float2 x0 = *reinterpret_cast<const float2*>(resid + r0 * ldr + gc);
                const float2 x1 = *reinterpret_cast<const float2*>(resid + r1 * ldr + gc);
                v0 += x0.x; v1 += x0.y; v2 += x1.x; v3 += x1.y;
            }
            *reinterpret_cast<float2*>(C + r0 * ldc + gc) = make_float2(v0, v1);
            *reinterpret_cast<float2*>(C + r1 * ldc + gc) = make_float2(v2, v3);
        }
    }
}

// ---------------------------------------------------------------------------
extern "C" void kernel_launch(void* const* d_in, const int* in_sizes, int n_in,
                              void* d_out, int out_size)
{
    const float* x    = (const float*)d_in[0];
    const float* nw   = (const float*)d_in[1];
    const float* rw   = (const float*)d_in[2];
    const float* rb   = (const float*)d_in[3];
    const float* qkv  = (const float*)d_in[4];
    const float* proj = (const float*)d_in[5];
    const float* pb   = (const float*)d_in[6];
    const float* ow   = (const float*)d_in[7];
    float* out = (float*)d_out;

    float *xn, *v, *eo, *rt;
    cudaGetSymbolAddress((void**)&xn, g_xn);
    cudaGetSymbolAddress((void**)&v,  g_v);
    cudaGetSymbolAddress((void**)&eo, g_eo);
    cudaGetSymbolAddress((void**)&rt, g_rt);

    // 1) RMSNorm + router
    rmsnorm_router_kernel<<<BROWS, 256>>>(x, nw, rw, rb, xn, rt);

    // 2) v = xs @ qkv_w[:, :, 2dE:]   (per expert, M=32768, N=512, K=512)
    gemm_tf32<0><<<dim3(4, 256, 4), 256>>>(
        xn, DMODEL, DEXP,
        qkv + 2 * DEXP, 3 * DEXP, (long long)DEXP * 3 * DEXP,
        v, DMODEL, DEXP,
        DEXP,
        nullptr, 0, nullptr, nullptr, 0);

    // 3) eo = (v @ proj_w + proj_b) * routing   (per expert)
    gemm_tf32<1><<<dim3(4, 256, 4), 256>>>(
        v, DMODEL, DEXP,
        proj, DEXP, (long long)DEXP * DEXP,
        eo, DMODEL, DEXP,
        DEXP,
        pb, DEXP, rt, nullptr, 0);

    // 4) out = x + eo @ out_w   (M=32768, N=2048, K=2048)
    gemm_tf32<2><<<dim3(16, 256, 1), 256>>>(
        eo, DMODEL, 0,
        ow, DMODEL, 0,
        out, DMODEL, 0,
        DMODEL,
        nullptr, 0, nullptr, x, DMODEL);
}

// round 4
// speedup vs baseline: 1.9107x; 1.9107x over previous
#include <cuda_runtime.h>
#include <cuda_fp16.h>
#include <cstdint>

// ---------------- problem constants ----------------
#define BROWS 32768
#define DMODEL 2048
#define NEXP 4
#define DEXP 512

// ---------------- device scratch (allocation-free rule) ----------------
__device__ __half g_xn [(size_t)BROWS * DMODEL];
__device__ __half g_v  [(size_t)BROWS * DMODEL];
__device__ __half g_eo [(size_t)BROWS * DMODEL];
__device__ float  g_rt [(size_t)BROWS * NEXP];
__device__ __half g_qvt[(size_t)NEXP * DEXP * DEXP];   // qkv V-slice, [e][n][k]
__device__ __half g_pjt[(size_t)NEXP * DEXP * DEXP];   // proj,        [e][n][k]
__device__ __half g_owt[(size_t)DMODEL * DMODEL];      // out_w,       [n][k]

__device__ __forceinline__ uint32_t smem_u32(const void* p) {
    uint32_t a;
    asm("{ .reg .u64 t; cvta.to.shared.u64 t, %1; cvt.u32.u64 %0, t; }" : "=r"(a) : "l"(p));
    return a;
}

#define CP16(dst, src) \
    asm volatile("cp.async.cg.shared.global [%0], [%1], 16;\n" :: "r"(dst), "l"(src))

#define LDSM_X4(r0, r1, r2, r3, addr) \
    asm volatile("ldmatrix.sync.aligned.m8n8.x4.shared.b16 {%0,%1,%2,%3}, [%4];" \
        : "=r"(r0), "=r"(r1), "=r"(r2), "=r"(r3) : "r"(addr))

// ---------------------------------------------------------------------------
// Kernel 0: RMSNorm + router softmax; writes xn as fp16 (rn)
// ---------------------------------------------------------------------------
__global__ void __launch_bounds__(256)
rmsnorm_router_kernel(const float* __restrict__ x, const float* __restrict__ nw,
                      const float* __restrict__ rw, const float* __restrict__ rb,
                      __half* __restrict__ xn, float* __restrict__ routing)
{
    __shared__ float red[8];
    __shared__ float red4[8][4];
    __shared__ float s_rn;

    const int b = blockIdx.x;
    const int tid = threadIdx.x;
    const int lane = tid & 31, warp = tid >> 5;

    const float4* xr = reinterpret_cast<const float4*>(x + (size_t)b * DMODEL);
    float4 v0 = xr[tid];
    float4 v1 = xr[tid + 256];

    float ss = v0.x*v0.x + v0.y*v0.y + v0.z*v0.z + v0.w*v0.w
             + v1.x*v1.x + v1.y*v1.y + v1.z*v1.z + v1.w*v1.w;
    #pragma unroll
    for (int o = 16; o; o >>= 1) ss += __shfl_xor_sync(0xffffffffu, ss, o);
    if (lane == 0) red[warp] = ss;
    __syncthreads();
    if (tid == 0) {
        float t = 0.f;
        #pragma unroll
        for (int i = 0; i < 8; i++) t += red[i];
        s_rn = rsqrtf(t * (1.0f / DMODEL) + 1e-6f);
    }
    __syncthreads();
    const float rn = s_rn;

    const float4* nwr = reinterpret_cast<const float4*>(nw);
    float4 w0 = nwr[tid], w1 = nwr[tid + 256];
    float4 y0 = make_float4(v0.x*rn*w0.x, v0.y*rn*w0.y, v0.z*rn*w0.z, v0.w*rn*w0.w);
    float4 y1 = make_float4(v1.x*rn*w1.x, v1.y*rn*w1.y, v1.z*rn*w1.z, v1.w*rn*w1.w);

    __half2* xo = reinterpret_cast<__half2*>(xn + (size_t)b * DMODEL);
    xo[tid * 2]             = __floats2half2_rn(y0.x, y0.y);
    xo[tid * 2 + 1]         = __floats2half2_rn(y0.z, y0.w);
    xo[(tid + 256) * 2]     = __floats2half2_rn(y1.x, y1.y);
    xo[(tid + 256) * 2 + 1] = __floats2half2_rn(y1.z, y1.w);

    const float4* rwr = reinterpret_cast<const float4*>(rw);
    float a0 = 0.f, a1 = 0.f, a2 = 0.f, a3 = 0.f;
    const int d0 = tid * 4;
    const int d1 = (tid + 256) * 4;
    float ys[8] = {y0.x, y0.y, y0.z, y0.w, y1.x, y1.y, y1.z, y1.w};
    int   ds[8] = {d0, d0+1, d0+2, d0+3, d1, d1+1, d1+2, d1+3};
    #pragma unroll
    for (int i = 0; i < 8; i++) {
        float4 w = rwr[ds[i]];
        a0 += ys[i] * w.x; a1 += ys[i] * w.y; a2 += ys[i] * w.z; a3 += ys[i] * w.w;
    }
    #pragma unroll
    for (int o = 16; o; o >>= 1) {
        a0 += __shfl_xor_sync(0xffffffffu, a0, o);
        a1 += __shfl_xor_sync(0xffffffffu, a1, o);
        a2 += __shfl_xor_sync(0xffffffffu, a2, o);
        a3 += __shfl_xor_sync(0xffffffffu, a3, o);
    }
    if (lane == 0) { red4[warp][0]=a0; red4[warp][1]=a1; red4[warp][2]=a2; red4[warp][3]=a3; }
    __syncthreads();
    if (tid == 0) {
        float l[4];
        #pragma unroll
        for (int e = 0; e < 4; e++) {
            l[e] = rb[e];
            #pragma unroll
            for (int i = 0; i < 8; i++) l[e] += red4[i][e];
        }
        float m = fmaxf(fmaxf(l[0], l[1]), fmaxf(l[2], l[3]));
        float p[4], s = 0.f;
        #pragma unroll
        for (int e = 0; e < 4; e++) { p[e] = expf(l[e] - m); s += p[e]; }
        float inv = 1.0f / s;
        #pragma unroll
        for (int e = 0; e < 4; e++) routing[(size_t)b * 4 + e] = p[e] * inv;
    }
}

// ---------------------------------------------------------------------------
// Weight transpose + fp16 round: out[e][n][k] = half(in[e][k][col_off + n])
// ---------------------------------------------------------------------------
__global__ void __launch_bounds__(256)
transpose_h(const float* __restrict__ in, __half* __restrict__ out,
            int src_ld, int col_off, int Kdim,
            long long in_es, long long out_es)
{
    __shared__ float t[32][33];
    const int e = blockIdx.z;
    in  += (long long)e * in_es;
    out += (long long)e * out_es;
    const int k0 = blockIdx.x * 32, n0 = blockIdx.y * 32;
    const int txx = threadIdx.x % 32;
    const int tyy = threadIdx.x / 32;   // 0..7
    #pragma unroll
    for (int i = 0; i < 32; i += 8)
        t[tyy + i][txx] = in[(size_t)(k0 + tyy + i) * src_ld + col_off + n0 + txx];
    __syncthreads();
    #pragma unroll
    for (int i = 0; i < 32; i += 8)
        out[(size_t)(n0 + tyy + i) * Kdim + k0 + txx] = __float2half_rn(t[txx][tyy + i]);
}

// ---------------------------------------------------------------------------
// fp16 tensor-core GEMM: C[M,N] = A[M,K] @ Bt[N,K]^T
// BM=128, BN=256, BK=32, 4-stage cp.async, ldmatrix frags, 80B row pitch.
// 8 warps as 2(M) x 4(N): warp tile 64x64.
// MODE 0: C(half) = A@B
// MODE 1: C(half) = (A@B + bias) * routing
// MODE 2: C(float) = A@B + resid
// ---------------------------------------------------------------------------
static constexpr int G_BM = 128, G_BN = 256, G_BK = 32, G_STAGES = 4;
static constexpr int G_PITCH = 80;                          // bytes per smem row
static constexpr int G_ABYTES = G_BM * G_PITCH;             // 10240
static constexpr int G_BBYTES = G_BN * G_PITCH;             // 20480
static constexpr int G_STAGE  = G_ABYTES + G_BBYTES;        // 30720
static constexpr int G_SMEM   = G_STAGES * G_STAGE;         // 122880

template<int MODE>
__global__ void __launch_bounds__(256, 1)
gemm_h(const __half* __restrict__ A, int lda, int aColStep,
       const __half* __restrict__ Bt, int ldb, long long sB,
       void* __restrict__ Cv, int ldc, int cColStep,
       int K,
       const float* __restrict__ bias,
       const float* __restrict__ routing,
       const float* __restrict__ resid)
{
    extern __shared__ char smem[];
    const uint32_t sbase = smem_u32(smem);

    const int tid = threadIdx.x, lane = tid & 31, warp = tid >> 5;
    const int bn = blockIdx.x, bm = blockIdx.y, e = blockIdx.z;
    const int wm = warp & 1, wn = warp >> 1;
    const int m_base = wm * 64, n_base = wn * 64;

    const __half* Ag = A + (size_t)(bm * G_BM) * lda + e * aColStep;
    const __half* Bg = Bt + (long long)e * sB + (size_t)(bn * G_BN) * ldb;

    // cp.async layout
    const int arow = tid >> 2, ac = tid & 3;

    auto load_stage = [&](int s, int kt) {
        const uint32_t as = sbase + s * G_STAGE;
        const uint32_t bs = as + G_ABYTES;
        const int k0 = kt * G_BK;
        CP16(as + (uint32_t)(arow * G_PITCH + ac * 16),
             Ag + (size_t)arow * lda + k0 + ac * 8);
        CP16(as + (uint32_t)((arow + 64) * G_PITCH + ac * 16),
             Ag + (size_t)(arow + 64) * lda + k0 + ac * 8);
        #pragma unroll
        for (int i = 0; i < 4; i++)
            CP16(bs + (uint32_t)((arow + 64 * i) * G_PITCH + ac * 16),
                 Bg + (size_t)(arow + 64 * i) * ldb + k0 + ac * 8);
        asm volatile("cp.async.commit_group;\n" ::);
    };

    // ldmatrix per-thread address bases
    const int mt = lane >> 3, rr = lane & 7;
    const uint32_t aAddr0 = sbase +
        (uint32_t)((m_base + (mt & 1) * 8 + rr) * G_PITCH + (mt >> 1) * 16);
    const uint32_t bAddr0 = sbase + (uint32_t)G_ABYTES +
        (uint32_t)((n_base + (mt >> 1) * 8 + rr) * G_PITCH + (mt & 1) * 16);

    float acc[4][8][4];
    #pragma unroll
    for (int f = 0; f < 4; f++)
        #pragma unroll
        for (int g = 0; g < 8; g++)
            #pragma unroll
            for (int i = 0; i < 4; i++) acc[f][g][i] = 0.f;

    const int NT = K / G_BK;
    // prologue: 3 stages
    load_stage(0, 0);
    load_stage(1, 1);
    load_stage(2, 2);

    for (int kt = 0; kt < NT; kt++) {
        asm volatile("cp.async.wait_group 2;\n" ::);
        __syncthreads();
        if (kt + 3 < NT) load_stage((kt + 3) & 3, kt + 3);

        const uint32_t so = (kt & 3) * G_STAGE;
        #pragma unroll
        for (int ks = 0; ks < 2; ks++) {
            uint32_t a[4][4], b[4][4];
            #pragma unroll
            for (int f = 0; f < 4; f++)
                LDSM_X4(a[f][0], a[f][1], a[f][2], a[f][3],
                        aAddr0 + so + (uint32_t)(f * 16 * G_PITCH + ks * 32));
            #pragma unroll
            for (int gp = 0; gp < 4; gp++)
                LDSM_X4(b[gp][0], b[gp][1], b[gp][2], b[gp][3],
                        bAddr0 + so + (uint32_t)(gp * 16 * G_PITCH + ks * 32));
            #pragma unroll
            for (int f = 0; f < 4; f++)
                #pragma unroll
                for (int g = 0; g < 8; g++) {
                    float* d = acc[f][g];
                    const uint32_t b0 = b[g >> 1][(g & 1) * 2];
                    const uint32_t b1 = b[g >> 1][(g & 1) * 2 + 1];
                    asm volatile(
                        "mma.sync.aligned.m16n8k16.row.col.f32.f16.f16.f32 "
                        "{%0,%1,%2,%3}, {%4,%5,%6,%7}, {%8,%9}, {%0,%1,%2,%3};\n"
                        : "+f"(d[0]), "+f"(d[1]), "+f"(d[2]), "+f"(d[3])
                        : "r"(a[f][0]), "r"(a[f][1]), "r"(a[f][2]), "r"(a[f][3]),
                          "r"(b0), "r"(b1));
                }
        }
        __syncthreads();
    }

    // ---------------- epilogue ----------------
    const int gid = lane >> 2, tig = lane & 3;
    const int cColBase = e * cColStep + bn * G_BN;

    #pragma unroll
    for (int f = 0; f < 4; f++) {
        const size_t r0 = (size_t)bm * G_BM + m_base + f * 16 + gid;
        const size_t r1 = r0 + 8;
        float rt0 = 1.f, rt1 = 1.f;
        if (MODE == 1) {
            rt0 = routing[r0 * 4 + e];
            rt1 = routing[r1 * 4 + e];
        }
        #pragma unroll
        for (int g = 0; g < 8; g++) {
            const int ncl = n_base + g * 8 + tig * 2;   // col within block tile
            const int gc = cColBase + ncl;
            float v0 = acc[f][g][0], v1 = acc[f][g][1];
            float v2 = acc[f][g][2], v3 = acc[f][g][3];
            if (MODE == 1) {
                const float b0 = bias[e * DEXP + bn * G_BN + ncl];
                const float b1 = bias[e * DEXP + bn * G_BN + ncl + 1];
                v0 = (v0 + b0) * rt0; v1 = (v1 + b1) * rt0;
                v2 = (v2 + b0) * rt1; v3 = (v3 + b1) * rt1;
            }
            if (MODE == 2) {
                float* C = (float*)Cv;
                const float2 x0 = *reinterpret_cast<const float2*>(resid + r0 * ldc + gc);
                const float2 x1 = *reinterpret_cast<const float2*>(resid + r1 * ldc + gc);
                *reinterpret_cast<float2*>(C + r0 * ldc + gc) = make_float2(v0 + x0.x, v1 + x0.y);
                *reinterpret_cast<float2*>(C + r1 * ldc + gc) = make_float2(v2 + x1.x, v3 + x1.y);
            } else {
                __half* C = (__half*)Cv;
                *reinterpret_cast<__half2*>(C + r0 * ldc + gc) = __floats2half2_rn(v0, v1);
                *reinterpret_cast<__half2*>(C + r1 * ldc + gc) = __floats2half2_rn(v2, v3);
            }
        }
    }
}

// ---------------------------------------------------------------------------
extern "C" void kernel_launch(void* const* d_in, const int* in_sizes, int n_in,
                              void* d_out, int out_size)
{
    const float* x    = (const float*)d_in[0];
    const float* nw   = (const float*)d_in[1];
    const float* rw   = (const float*)d_in[2];
    const float* rb   = (const float*)d_in[3];
    const float* qkv  = (const float*)d_in[4];
    const float* proj = (const float*)d_in[5];
    const float* pb   = (const float*)d_in[6];
    const float* ow   = (const float*)d_in[7];
    float* out = (float*)d_out;

    __half *xn, *v, *eo, *qvt, *pjt, *owt;
    float *rt;
    cudaGetSymbolAddress((void**)&xn,  g_xn);
    cudaGetSymbolAddress((void**)&v,   g_v);
    cudaGetSymbolAddress((void**)&eo,  g_eo);
    cudaGetSymbolAddress((void**)&rt,  g_rt);
    cudaGetSymbolAddress((void**)&qvt, g_qvt);
    cudaGetSymbolAddress((void**)&pjt, g_pjt);
    cudaGetSymbolAddress((void**)&owt, g_owt);

    static bool s_attr_done = false;
    if (!s_attr_done) {
        cudaFuncSetAttribute(gemm_h<0>, cudaFuncAttributeMaxDynamicSharedMemorySize, G_SMEM);
        cudaFuncSetAttribute(gemm_h<1>, cudaFuncAttributeMaxDynamicSharedMemorySize, G_SMEM);
        cudaFuncSetAttribute(gemm_h<2>, cudaFuncAttributeMaxDynamicSharedMemorySize, G_SMEM);
        s_attr_done = true;
    }

    // 1) RMSNorm + router (writes fp16 xn, fp32 routing)
    rmsnorm_router_kernel<<<BROWS, 256>>>(x, nw, rw, rb, xn, rt);

    // 2) weight transposes (+ fp16 round)
    transpose_h<<<dim3(16, 16, 4), 256>>>(qkv, qvt, 3 * DEXP, 2 * DEXP, DEXP,
                                          (long long)DEXP * 3 * DEXP, (long long)DEXP * DEXP);
    transpose_h<<<dim3(16, 16, 4), 256>>>(proj, pjt, DEXP, 0, DEXP,
                                          (long long)DEXP * DEXP, (long long)DEXP * DEXP);
    transpose_h<<<dim3(64, 64, 1), 256>>>(ow, owt, DMODEL, 0, DMODEL, 0, 0);

    // 3) v = xs @ qkv_w[:,:,2dE:]   per expert: M=32768, N=512, K=512
    gemm_h<0><<<dim3(2, 256, 4), 256, G_SMEM>>>(
        xn, DMODEL, DEXP, qvt, DEXP, (long long)DEXP * DEXP,
        v, DMODEL, DEXP, DEXP, nullptr, nullptr, nullptr);

    // 4) eo = (v @ proj + pb) * routing
    gemm_h<1><<<dim3(2, 256, 4), 256, G_SMEM>>>(
        v, DMODEL, DEXP, pjt, DEXP, (long long)DEXP * DEXP,
        eo, DMODEL, DEXP, DEXP, pb, rt, nullptr);

    // 5) out = x + eo @ out_w       M=32768, N=2048, K=2048
    gemm_h<2><<<dim3(8, 256, 1), 256, G_SMEM>>>(
        eo, DMODEL, 0, owt, DMODEL, 0,
        out, DMODEL, 0, DMODEL, nullptr, nullptr, x);
}

// round 5
// speedup vs baseline: 2.1713x; 1.1364x over previous
#include <cuda_runtime.h>
#include <cuda_fp16.h>
#include <cstdint>

// ---------------- problem constants ----------------
#define BROWS 32768
#define DMODEL 2048
#define NEXP 4
#define DEXP 512

// ---------------- device scratch (allocation-free rule) ----------------
__device__ __half g_xn [(size_t)BROWS * DMODEL];
__device__ __half g_v  [(size_t)BROWS * DMODEL];
__device__ __half g_eo [(size_t)BROWS * DMODEL];
__device__ float  g_rt [(size_t)BROWS * NEXP];
__device__ __half g_qvt[(size_t)NEXP * DEXP * DEXP];   // qkv V-slice, [e][n][k]
__device__ __half g_pjt[(size_t)NEXP * DEXP * DEXP];   // proj,        [e][n][k]
__device__ __half g_owt[(size_t)DMODEL * DMODEL];      // out_w,       [n][k]

__device__ __forceinline__ uint32_t smem_u32(const void* p) {
    uint32_t a;
    asm("{ .reg .u64 t; cvta.to.shared.u64 t, %1; cvt.u32.u64 %0, t; }" : "=r"(a) : "l"(p));
    return a;
}

#define CP16(dst, src) \
    asm volatile("cp.async.cg.shared.global [%0], [%1], 16;\n" :: "r"(dst), "l"(src))

#define LDSM_X4(r0, r1, r2, r3, addr) \
    asm volatile("ldmatrix.sync.aligned.m8n8.x4.shared.b16 {%0,%1,%2,%3}, [%4];" \
        : "=r"(r0), "=r"(r1), "=r"(r2), "=r"(r3) : "r"(addr))

// ---------------------------------------------------------------------------
// Kernel 0: RMSNorm + router softmax; writes xn as fp16 (rn)
// ---------------------------------------------------------------------------
__global__ void __launch_bounds__(256)
rmsnorm_router_kernel(const float* __restrict__ x, const float* __restrict__ nw,
                      const float* __restrict__ rw, const float* __restrict__ rb,
                      __half* __restrict__ xn, float* __restrict__ routing)
{
    __shared__ float red[8];
    __shared__ float red4[8][4];
    __shared__ float s_rn;

    const int b = blockIdx.x;
    const int tid = threadIdx.x;
    const int lane = tid & 31, warp = tid >> 5;

    const float4* xr = reinterpret_cast<const float4*>(x + (size_t)b * DMODEL);
    float4 v0 = xr[tid];
    float4 v1 = xr[tid + 256];

    float ss = v0.x*v0.x + v0.y*v0.y + v0.z*v0.z + v0.w*v0.w
             + v1.x*v1.x + v1.y*v1.y + v1.z*v1.z + v1.w*v1.w;
    #pragma unroll
    for (int o = 16; o; o >>= 1) ss += __shfl_xor_sync(0xffffffffu, ss, o);
    if (lane == 0) red[warp] = ss;
    __syncthreads();
    if (tid == 0) {
        float t = 0.f;
        #pragma unroll
        for (int i = 0; i < 8; i++) t += red[i];
        s_rn = rsqrtf(t * (1.0f / DMODEL) + 1e-6f);
    }
    __syncthreads();
    const float rn = s_rn;

    const float4* nwr = reinterpret_cast<const float4*>(nw);
    float4 w0 = nwr[tid], w1 = nwr[tid + 256];
    float4 y0 = make_float4(v0.x*rn*w0.x, v0.y*rn*w0.y, v0.z*rn*w0.z, v0.w*rn*w0.w);
    float4 y1 = make_float4(v1.x*rn*w1.x, v1.y*rn*w1.y, v1.z*rn*w1.z, v1.w*rn*w1.w);

    __half2* xo = reinterpret_cast<__half2*>(xn + (size_t)b * DMODEL);
    xo[tid * 2]             = __floats2half2_rn(y0.x, y0.y);
    xo[tid * 2 + 1]         = __floats2half2_rn(y0.z, y0.w);
    xo[(tid + 256) * 2]     = __floats2half2_rn(y1.x, y1.y);
    xo[(tid + 256) * 2 + 1] = __floats2half2_rn(y1.z, y1.w);

    const float4* rwr = reinterpret_cast<const float4*>(rw);
    float a0 = 0.f, a1 = 0.f, a2 = 0.f, a3 = 0.f;
    const int d0 = tid * 4;
    const int d1 = (tid + 256) * 4;
    float ys[8] = {y0.x, y0.y, y0.z, y0.w, y1.x, y1.y, y1.z, y1.w};
    int   ds[8] = {d0, d0+1, d0+2, d0+3, d1, d1+1, d1+2, d1+3};
    #pragma unroll
    for (int i = 0; i < 8; i++) {
        float4 w = rwr[ds[i]];
        a0 += ys[i] * w.x; a1 += ys[i] * w.y; a2 += ys[i] * w.z; a3 += ys[i] * w.w;
    }
    #pragma unroll
    for (int o = 16; o; o >>= 1) {
        a0 += __shfl_xor_sync(0xffffffffu, a0, o);
        a1 += __shfl_xor_sync(0xffffffffu, a1, o);
        a2 += __shfl_xor_sync(0xffffffffu, a2, o);
        a3 += __shfl_xor_sync(0xffffffffu, a3, o);
    }
    if (lane == 0) { red4[warp][0]=a0; red4[warp][1]=a1; red4[warp][2]=a2; red4[warp][3]=a3; }
    __syncthreads();
    if (tid == 0) {
        float l[4];
        #pragma unroll
        for (int e = 0; e < 4; e++) {
            l[e] = rb[e];
            #pragma unroll
            for (int i = 0; i < 8; i++) l[e] += red4[i][e];
        }
        float m = fmaxf(fmaxf(l[0], l[1]), fmaxf(l[2], l[3]));
        float p[4], s = 0.f;
        #pragma unroll
        for (int e = 0; e < 4; e++) { p[e] = expf(l[e] - m); s += p[e]; }
        float inv = 1.0f / s;
        #pragma unroll
        for (int e = 0; e < 4; e++) routing[(size_t)b * 4 + e] = p[e] * inv;
    }
}

// ---------------------------------------------------------------------------
// Weight transpose + fp16 round: out[e][n][k] = half(in[e][k][col_off + n])
// ---------------------------------------------------------------------------
__global__ void __launch_bounds__(256)
transpose_h(const float* __restrict__ in, __half* __restrict__ out,
            int src_ld, int col_off, int Kdim,
            long long in_es, long long out_es)
{
    __shared__ float t[32][33];
    const int e = blockIdx.z;
    in  += (long long)e * in_es;
    out += (long long)e * out_es;
    const int k0 = blockIdx.x * 32, n0 = blockIdx.y * 32;
    const int txx = threadIdx.x % 32;
    const int tyy = threadIdx.x / 32;   // 0..7
    #pragma unroll
    for (int i = 0; i < 32; i += 8)
        t[tyy + i][txx] = in[(size_t)(k0 + tyy + i) * src_ld + col_off + n0 + txx];
    __syncthreads();
    #pragma unroll
    for (int i = 0; i < 32; i += 8)
        out[(size_t)(n0 + tyy + i) * Kdim + k0 + txx] = __float2half_rn(t[txx][tyy + i]);
}

// ---------------------------------------------------------------------------
// fp16 tensor-core GEMM: C[M,N] = A[M,K] @ Bt[N,K]^T
// BM=128, BN=256, BK=64, 3-stage cp.async, ldmatrix frag ping-pong,
// 144B row pitch (conflict-free), single __syncthreads per k-tile.
// 8 warps as 2(M) x 4(N): warp tile 64x64.
// MODE 0: C(half) = A@B
// MODE 1: C(half) = (A@B + bias) * routing
// MODE 2: C(float) = A@B + resid
// ---------------------------------------------------------------------------
static constexpr int G_BM = 128, G_BN = 256, G_BK = 64, G_STAGES = 3;
static constexpr int G_PITCH = 144;                         // bytes per smem row
static constexpr int G_ABYTES = G_BM * G_PITCH;             // 18432
static constexpr int G_BBYTES = G_BN * G_PITCH;             // 36864
static constexpr int G_STAGE  = G_ABYTES + G_BBYTES;        // 55296
static constexpr int G_SMEM   = G_STAGES * G_STAGE;         // 165888

template<int MODE>
__global__ void __launch_bounds__(256, 1)
gemm_h(const __half* __restrict__ A, int lda, int aColStep,
       const __half* __restrict__ Bt, int ldb, long long sB,
       void* __restrict__ Cv, int ldc, int cColStep,
       int K,
       const float* __restrict__ bias,
       const float* __restrict__ routing,
       const float* __restrict__ resid)
{
    extern __shared__ char smem[];
    const uint32_t sbase = smem_u32(smem);

    const int tid = threadIdx.x, lane = tid & 31, warp = tid >> 5;
    const int bn = blockIdx.x, bm = blockIdx.y, e = blockIdx.z;
    const int wm = warp & 1, wn = warp >> 1;
    const int m_base = wm * 64, n_base = wn * 64;

    const __half* Ag = A + (size_t)(bm * G_BM) * lda + e * aColStep;
    const __half* Bg = Bt + (long long)e * sB + (size_t)(bn * G_BN) * ldb;

    // cp.async layout: row = tid>>3 (0..31), chunk = tid&7 (16B each, 8 per 128B row)
    const int arow = tid >> 3, ac = tid & 7;

    auto load_stage = [&](int s, int kt) {
        const uint32_t as = sbase + s * G_STAGE;
        const uint32_t bs = as + G_ABYTES;
        const int k0 = kt * G_BK;
        #pragma unroll
        for (int i = 0; i < 4; i++)
            CP16(as + (uint32_t)((arow + 32 * i) * G_PITCH + ac * 16),
                 Ag + (size_t)(arow + 32 * i) * lda + k0 + ac * 8);
        #pragma unroll
        for (int i = 0; i < 8; i++)
            CP16(bs + (uint32_t)((arow + 32 * i) * G_PITCH + ac * 16),
                 Bg + (size_t)(arow + 32 * i) * ldb + k0 + ac * 8);
        asm volatile("cp.async.commit_group;\n" ::);
    };

    // ldmatrix per-thread address bases
    const int mt = lane >> 3, rr = lane & 7;
    const uint32_t aAddr0 = sbase +
        (uint32_t)((m_base + (mt & 1) * 8 + rr) * G_PITCH + (mt >> 1) * 16);
    const uint32_t bAddr0 = sbase + (uint32_t)G_ABYTES +
        (uint32_t)((n_base + (mt >> 1) * 8 + rr) * G_PITCH + (mt & 1) * 16);

    float acc[4][8][4];
    #pragma unroll
    for (int f = 0; f < 4; f++)
        #pragma unroll
        for (int g = 0; g < 8; g++)
            #pragma unroll
            for (int i = 0; i < 4; i++) acc[f][g][i] = 0.f;

    uint32_t a[2][4][4], b[2][4][4];

    const int NT = K / G_BK;
    // prologue: 2 stages in flight
    load_stage(0, 0);
    load_stage(1, 1);

    for (int kt = 0; kt < NT; kt++) {
        asm volatile("cp.async.wait_group 1;\n" ::);
        __syncthreads();
        if (kt + 2 < NT) load_stage((kt + 2) % 3, kt + 2);

        const uint32_t so = (uint32_t)((kt % 3) * G_STAGE);

        // prime frags for ks=0
        #pragma unroll
        for (int f = 0; f < 4; f++)
            LDSM_X4(a[0][f][0], a[0][f][1], a[0][f][2], a[0][f][3],
                    aAddr0 + so + (uint32_t)(f * 16 * G_PITCH));
        #pragma unroll
        for (int gp = 0; gp < 4; gp++)
            LDSM_X4(b[0][gp][0], b[0][gp][1], b[0][gp][2], b[0][gp][3],
                    bAddr0 + so + (uint32_t)(gp * 16 * G_PITCH));

        #pragma unroll
        for (int ks = 0; ks < 4; ks++) {
            const int cur = ks & 1, nxt = cur ^ 1;
            if (ks < 3) {
                const uint32_t ko = so + (uint32_t)((ks + 1) * 32);
                #pragma unroll
                for (int f = 0; f < 4; f++)
                    LDSM_X4(a[nxt][f][0], a[nxt][f][1], a[nxt][f][2], a[nxt][f][3],
                            aAddr0 + ko + (uint32_t)(f * 16 * G_PITCH));
                #pragma unroll
                for (int gp = 0; gp < 4; gp++)
                    LDSM_X4(b[nxt][gp][0], b[nxt][gp][1], b[nxt][gp][2], b[nxt][gp][3],
                            bAddr0 + ko + (uint32_t)(gp * 16 * G_PITCH));
            }
            #pragma unroll
            for (int f = 0; f < 4; f++)
                #pragma unroll
                for (int g = 0; g < 8; g++) {
                    float* d = acc[f][g];
                    const uint32_t b0 = b[cur][g >> 1][(g & 1) * 2];
                    const uint32_t b1 = b[cur][g >> 1][(g & 1) * 2 + 1];
                    asm volatile(
                        "mma.sync.aligned.m16n8k16.row.col.f32.f16.f16.f32 "
                        "{%0,%1,%2,%3}, {%4,%5,%6,%7}, {%8,%9}, {%0,%1,%2,%3};\n"
                        : "+f"(d[0]), "+f"(d[1]), "+f"(d[2]), "+f"(d[3])
                        : "r"(a[cur][f][0]), "r"(a[cur][f][1]),
                          "r"(a[cur][f][2]), "r"(a[cur][f][3]),
                          "r"(b0), "r"(b1));
                }
        }
    }

    // ---------------- epilogue ----------------
    const int gid = lane >> 2, tig = lane & 3;
    const int cColBase = e * cColStep + bn * G_BN;

    #pragma unroll
    for (int f = 0; f < 4; f++) {
        const size_t r0 = (size_t)bm * G_BM + m_base + f * 16 + gid;
        const size_t r1 = r0 + 8;
        float rt0 = 1.f, rt1 = 1.f;
        if (MODE == 1) {
            rt0 = routing[r0 * 4 + e];
            rt1 = routing[r1 * 4 + e];
        }
        #pragma unroll
        for (int g = 0; g < 8; g++) {
            const int ncl = n_base + g * 8 + tig * 2;   // col within block tile
            const int gc = cColBase + ncl;
            float v0 = acc[f][g][0], v1 = acc[f][g][1];
            float v2 = acc[f][g][2], v3 = acc[f][g][3];
            if (MODE == 1) {
                const float b0 = bias[e * DEXP + bn * G_BN + ncl];
                const float b1 = bias[e * DEXP + bn * G_BN + ncl + 1];
                v0 = (v0 + b0) * rt0; v1 = (v1 + b1) * rt0;
                v2 = (v2 + b0) * rt1; v3 = (v3 + b1) * rt1;
            }
            if (MODE == 2) {
                float* C = (float*)Cv;
                const float2 x0 = *reinterpret_cast<const float2*>(resid + r0 * ldc + gc);
                const float2 x1 = *reinterpret_cast<const float2*>(resid + r1 * ldc + gc);
                *reinterpret_cast<float2*>(C + r0 * ldc + gc) = make_float2(v0 + x0.x, v1 + x0.y);
                *reinterpret_cast<float2*>(C + r1 * ldc + gc) = make_float2(v2 + x1.x, v3 + x1.y);
            } else {
                __half* C = (__half*)Cv;
                *reinterpret_cast<__half2*>(C + r0 * ldc + gc) = __floats2half2_rn(v0, v1);
                *reinterpret_cast<__half2*>(C + r1 * ldc + gc) = __floats2half2_rn(v2, v3);
            }
        }
    }
}

// ---------------------------------------------------------------------------
extern "C" void kernel_launch(void* const* d_in, const int* in_sizes, int n_in,
                              void* d_out, int out_size)
{
    const float* x    = (const float*)d_in[0];
    const float* nw   = (const float*)d_in[1];
    const float* rw   = (const float*)d_in[2];
    const float* rb   = (const float*)d_in[3];
    const float* qkv  = (const float*)d_in[4];
    const float* proj = (const float*)d_in[5];
    const float* pb   = (const float*)d_in[6];
    const float* ow   = (const float*)d_in[7];
    float* out = (float*)d_out;

    __half *xn, *v, *eo, *qvt, *pjt, *owt;
    float *rt;
    cudaGetSymbolAddress((void**)&xn,  g_xn);
    cudaGetSymbolAddress((void**)&v,   g_v);
    cudaGetSymbolAddress((void**)&eo,  g_eo);
    cudaGetSymbolAddress((void**)&rt,  g_rt);
    cudaGetSymbolAddress((void**)&qvt, g_qvt);
    cudaGetSymbolAddress((void**)&pjt, g_pjt);
    cudaGetSymbolAddress((void**)&owt, g_owt);

    cudaFuncSetAttribute(gemm_h<0>, cudaFuncAttributeMaxDynamicSharedMemorySize, G_SMEM);
    cudaFuncSetAttribute(gemm_h<1>, cudaFuncAttributeMaxDynamicSharedMemorySize, G_SMEM);
    cudaFuncSetAttribute(gemm_h<2>, cudaFuncAttributeMaxDynamicSharedMemorySize, G_SMEM);

    // 1) RMSNorm + router (writes fp16 xn, fp32 routing)
    rmsnorm_router_kernel<<<BROWS, 256>>>(x, nw, rw, rb, xn, rt);

    // 2) weight transposes (+ fp16 round)
    transpose_h<<<dim3(16, 16, 4), 256>>>(qkv, qvt, 3 * DEXP, 2 * DEXP, DEXP,
                                          (long long)DEXP * 3 * DEXP, (long long)DEXP * DEXP);
    transpose_h<<<dim3(16, 16, 4), 256>>>(proj, pjt, DEXP, 0, DEXP,
                                          (long long)DEXP * DEXP, (long long)DEXP * DEXP);
    transpose_h<<<dim3(64, 64, 1), 256>>>(ow, owt, DMODEL, 0, DMODEL, 0, 0);

    // 3) v = xs @ qkv_w[:,:,2dE:]   per expert: M=32768, N=512, K=512
    gemm_h<0><<<dim3(2, 256, 4), 256, G_SMEM>>>(
        xn, DMODEL, DEXP, qvt, DEXP, (long long)DEXP * DEXP,
        v, DMODEL, DEXP, DEXP, nullptr, nullptr, nullptr);

    // 4) eo = (v @ proj + pb) * routing
    gemm_h<1><<<dim3(2, 256, 4), 256, G_SMEM>>>(
        v, DMODEL, DEXP, pjt, DEXP, (long long)DEXP * DEXP,
        eo, DMODEL, DEXP, DEXP, pb, rt, nullptr);

    // 5) out = x + eo @ out_w       M=32768, N=2048, K=2048
    gemm_h<2><<<dim3(8, 256, 1), 256, G_SMEM>>>(
        eo, DMODEL, 0, owt, DMODEL, 0,
        out, DMODEL, 0, DMODEL, nullptr, nullptr, x);
}